// round 15
// baseline (speedup 1.0000x reference)
#include <cuda_runtime.h>
#include <math.h>

// Problem constants
#define BQ 4
#define MQ 2048
#define KQ 64
#define CQ 64
#define SRQ 16
#define PPQ 28

// Output layout: occ (B,M) | sdf (B,M,K) | inter (B,M,C) | support (B,M,K)
#define OUT_OCC   0
#define OUT_SDF   (BQ*MQ)
#define OUT_INTER (OUT_SDF + BQ*MQ*KQ)
#define OUT_SUP   (OUT_INTER + BQ*MQ*CQ)

// Inter-kernel / intra-grid scratch (static __device__, allocation-free)
__device__ float  g_occ[BQ*MQ*KQ];          // 2 MB
__device__ float2 g_curve[BQ*KQ*64];        // 128 KB
__device__ float  g_prim[BQ*KQ*8];          // 8 KB
__device__ int    g_flag[32];               // per-(b,ktile8) ready flags

__device__ __forceinline__ float ex2f(float x) {
    float r;
    asm("ex2.approx.ftz.f32 %0, %1;" : "=f"(r) : "f"(x));
    return r;
}

// winding edge, BIT-PARITY form (see R12): crossing needs only signs;
// one LOP3 for (ryb^nyb)&(crb^nyb), one LOP3 XOR-accumulate.
#define EDGE2(rx, ry, parb, nx_, ny_)                                    \
    {                                                                    \
        float cr = fmaf(rx, (ny_), -((ry)*(nx_)));                       \
        parb ^= (__float_as_int(ry) ^ __float_as_int(ny_))               \
              & (__float_as_int(cr) ^ __float_as_int(ny_));              \
        rx = (nx_); ry = (ny_);                                          \
    }

// rotate (x,y) by i*90 degrees (i in 0..3)
__device__ __forceinline__ float2 rot90(int i, float x, float y) {
    switch (i & 3) {
        case 0:  return make_float2( x,  y);
        case 1:  return make_float2(-y,  x);
        case 2:  return make_float2(-x, -y);
        default: return make_float2( y, -x);
    }
}

// theta = 2*pi/16 + atan(tan(2*pi/16)/3) = 0.529902783
#define CT 0.86285621f   // cos(theta)
#define ST 0.50544945f   // sin(theta)

// ============================ K1: SDF =====================================
// grid: (x = b*8+ktile8 = 32, y = mtile = 32) = 1024 blocks, 256 threads.
// Block = 8k x 64m; thread = 2 cells (m, m+32) of one k (warp k-uniform, ILP2).
// y==0 blocks are producers: build curve+prim into global, release g_flag[x].
#define K1_MT 64
#define K1_KT 8
#define K1_THREADS 256
#define K1P 65

#define K1_OFF_CURVE 0                           // 8*64 float2 = 1024 floats
#define K1_OFF_PRIM  1024
#define K1_OFF_SDF   (K1_OFF_PRIM + 64)
#define K1_OFF_DMIN  (K1_OFF_SDF + K1_KT*K1P)
#define K1_OFF_OCC   (K1_OFF_DMIN + K1_KT*K1P)
#define K1_SMEM      (K1_OFF_OCC + K1_KT*K1P)    // 2648 floats = 10592 B

__global__ __launch_bounds__(K1_THREADS, 6)
void sdf_kernel(const float* __restrict__ pts,   // (B,M,3)
                const float* __restrict__ prim,  // (B,28,K)
                float* __restrict__ out)
{
    extern __shared__ float sm[];
    float2* curve  = (float2*)(sm + K1_OFF_CURVE);
    float*  prim_s = sm + K1_OFF_PRIM;
    float*  sdf_s  = sm + K1_OFF_SDF;
    float*  dmin_s = sm + K1_OFF_DMIN;
    float*  occ_s  = sm + K1_OFF_OCC;

    const int tid = threadIdx.x;
    const int bx  = blockIdx.x;            // 0..31 = b*8 + ktile8
    const int b   = bx >> 3;
    const int k0  = (bx & 7) * K1_KT;
    const int m0  = blockIdx.y * K1_MT;

    // ---- Producer blocks (y==0) ----
    if (blockIdx.y == 0) {
        const float* P = prim + b * PPQ * KQ;
        if (tid < K1_KT) {
            const int k = k0 + tid;
            float q0 = P[0*KQ+k], q1 = P[1*KQ+k], q2 = P[2*KQ+k], q3 = P[3*KQ+k];
            float inv = rsqrtf(q0*q0 + q1*q1 + q2*q2 + q3*q3 + 1e-8f);
            float* gp = g_prim + (b*KQ + k)*8;
            gp[0] =  q0*inv;
            gp[1] = -q1*inv;
            gp[2] = -q2*inv;
            gp[3] = -q3*inv;
            gp[4] = P[4*KQ+k];
            gp[5] = P[5*KQ+k];
            gp[6] = P[6*KQ+k];
            gp[7] = fabsf(P[7*KQ+k]);
        }
        #pragma unroll
        for (int half = 0; half < 2; half++) {
            const int p   = tid + half*256;
            const int kli = p >> 6;
            const int k   = k0 + kli;
            const int s   = p & 63;
            const int seg = s >> 4;
            const int j   = s & 15;
            const int sn  = (seg + 1) & 3;
            const float r0 = fabsf(P[(8 + seg*3 + 0)*KQ + k]);
            const float r1 = fabsf(P[(8 + seg*3 + 1)*KQ + k]);
            const float r2 = fabsf(P[(8 + seg*3 + 2)*KQ + k]);
            const float rn = fabsf(P[(8 + sn*3  + 0)*KQ + k]);
            const float w1 = fabsf(P[(20 + seg*2 + 0)*KQ + k]);
            const float w2 = fabsf(P[(20 + seg*2 + 1)*KQ + k]);
            const float2 C0 = rot90(seg,   r0,     0.0f);
            const float2 C1 = rot90(seg,   r1*CT,  r1*ST);
            const float2 C2 = rot90(seg+1, r2*CT, -r2*ST);
            const float2 C3 = rot90(seg+1, rn,     0.0f);
            const float t  = j * (1.0f/SRQ);
            const float u1 = 1.0f - t;
            const float b0 = u1*u1*u1;
            const float b1 = 3.0f*u1*u1*t;
            const float b2 = 3.0f*u1*t*t;
            const float b3 = t*t*t;
            const float wb1 = w1*b1, wb2 = w2*b2;
            const float invd = __fdividef(1.0f, b0 + wb1 + wb2 + b3);
            g_curve[(b*KQ + k)*64 + s] = make_float2(
                (C0.x*b0 + C1.x*wb1 + C2.x*wb2 + C3.x*b3) * invd,
                (C0.y*b0 + C1.y*wb1 + C2.y*wb2 + C3.y*b3) * invd);
        }
        __threadfence();
        __syncthreads();
        if (tid == 0) atomicExch(&g_flag[bx], 1);
    }

    // ---- Acquire + stage curve/prim ----
    if (tid == 0) {
        while (atomicAdd(&g_flag[bx], 0) == 0) { __nanosleep(32); }
    }
    __syncthreads();
    {
        const float4* src = (const float4*)(g_curve + (b*KQ + k0)*64);
        float4* dst = (float4*)curve;
        dst[tid] = __ldcg(src + tid);
    }
    if (tid < K1_KT*8) prim_s[tid] = __ldcg(&g_prim[(b*KQ + k0)*8 + tid]);
    __syncthreads();

    // ---- Phase A: two cells (m, m+32) per thread ----
    const int m_local = tid & 31;
    const int kl      = tid >> 5;
    const int gm0     = b*MQ + m0 + m_local;
    const int gm1     = gm0 + 32;

    {
        const float* pr = prim_s + kl*8;
        const float qw = pr[0], qx = pr[1], qy = pr[2], qz = pr[3];
        const float tx = pr[4], ty = pr[5], tz = pr[6];
        const float h  = pr[7];

        float plx0, ply0, plz0;
        {
            const float ax = pts[gm0*3+0] - tx;
            const float ay = pts[gm0*3+1] - ty;
            const float az = pts[gm0*3+2] - tz;
            const float t2x = 2.0f*(qy*az - qz*ay);
            const float t2y = 2.0f*(qz*ax - qx*az);
            const float t2z = 2.0f*(qx*ay - qy*ax);
            plx0 = ax + qw*t2x + (qy*t2z - qz*t2y);
            ply0 = ay + qw*t2y + (qz*t2x - qx*t2z);
            plz0 = az + qw*t2z + (qx*t2y - qy*t2x);
        }
        float plx1, ply1, plz1;
        {
            const float ax = pts[gm1*3+0] - tx;
            const float ay = pts[gm1*3+1] - ty;
            const float az = pts[gm1*3+2] - tz;
            const float t2x = 2.0f*(qy*az - qz*ay);
            const float t2y = 2.0f*(qz*ax - qx*az);
            const float t2z = 2.0f*(qx*ay - qy*ax);
            plx1 = ax + qw*t2x + (qy*t2z - qz*t2y);
            ply1 = ay + qw*t2y + (qz*t2x - qx*t2z);
            plz1 = az + qw*t2z + (qx*t2y - qy*t2x);
        }

        const float4* cvp = (const float4*)(curve + kl*64);
        int parb0 = 0, parb1 = 0;
        float4 f0 = cvp[0];
        const float r0x0 = f0.x - plx0, r0y0 = f0.y - ply0;
        const float r0x1 = f0.x - plx1, r0y1 = f0.y - ply1;
        float rx0 = r0x0, ry0 = r0y0;
        float rx1 = r0x1, ry1 = r0y1;
        float d2a0 = fmaf(r0x0, r0x0, r0y0*r0y0);
        float d2a1 = fmaf(r0x1, r0x1, r0y1*r0y1);
        {
            float bx_ = f0.z - plx0, by_ = f0.w - ply0;
            d2a0 = fminf(d2a0, fmaf(bx_, bx_, by_*by_));
            EDGE2(rx0, ry0, parb0, bx_, by_);
            float cx_ = f0.z - plx1, cy_ = f0.w - ply1;
            d2a1 = fminf(d2a1, fmaf(cx_, cx_, cy_*cy_));
            EDGE2(rx1, ry1, parb1, cx_, cy_);
        }
        float d2b0 = 3.0e38f, d2b1 = 3.0e38f;
        #pragma unroll 4
        for (int s2 = 1; s2 < 32; s2++) {
            float4 g = cvp[s2];
            {
                float ax_ = g.x - plx0, ay_ = g.y - ply0;
                d2a0 = fminf(d2a0, fmaf(ax_, ax_, ay_*ay_));
                EDGE2(rx0, ry0, parb0, ax_, ay_);
                float bx_ = g.z - plx0, by_ = g.w - ply0;
                d2b0 = fminf(d2b0, fmaf(bx_, bx_, by_*by_));
                EDGE2(rx0, ry0, parb0, bx_, by_);
            }
            {
                float ax_ = g.x - plx1, ay_ = g.y - ply1;
                d2a1 = fminf(d2a1, fmaf(ax_, ax_, ay_*ay_));
                EDGE2(rx1, ry1, parb1, ax_, ay_);
                float bx_ = g.z - plx1, by_ = g.w - ply1;
                d2b1 = fminf(d2b1, fmaf(bx_, bx_, by_*by_));
                EDGE2(rx1, ry1, parb1, bx_, by_);
            }
        }
        EDGE2(rx0, ry0, parb0, r0x0, r0y0);
        EDGE2(rx1, ry1, parb1, r0x1, r0y1);

        {
            const float d2min = fminf(d2a0, d2b0);
            const float dmin  = sqrtf(d2min + 1e-12f);
            const float sdf2d = __int_as_float(__float_as_int(dmin)
                                               | (parb0 & 0x80000000));
            const float dz = fabsf(plz0) - h;
            const float e1 = fmaxf(sdf2d, 0.0f), e2 = fmaxf(dz, 0.0f);
            const float sdf = fminf(fmaxf(sdf2d, dz), 0.0f)
                            + sqrtf(e1*e1 + e2*e2 + 1e-12f);
            const float ex  = ex2f(fminf(216.404256f * sdf, 126.0f));
            const float occ = __fdividef(1.0f, 1.0f + ex);
            sdf_s [kl*K1P + m_local] = sdf;
            dmin_s[kl*K1P + m_local] = dmin;
            occ_s [kl*K1P + m_local] = occ;
        }
        {
            const float d2min = fminf(d2a1, d2b1);
            const float dmin  = sqrtf(d2min + 1e-12f);
            const float sdf2d = __int_as_float(__float_as_int(dmin)
                                               | (parb1 & 0x80000000));
            const float dz = fabsf(plz1) - h;
            const float e1 = fmaxf(sdf2d, 0.0f), e2 = fmaxf(dz, 0.0f);
            const float sdf = fminf(fmaxf(sdf2d, dz), 0.0f)
                            + sqrtf(e1*e1 + e2*e2 + 1e-12f);
            const float ex  = ex2f(fminf(216.404256f * sdf, 126.0f));
            const float occ = __fdividef(1.0f, 1.0f + ex);
            sdf_s [kl*K1P + m_local + 32] = sdf;
            dmin_s[kl*K1P + m_local + 32] = dmin;
            occ_s [kl*K1P + m_local + 32] = occ;
        }
    }
    __syncthreads();

    // ---- Flush coalesced: 64m x 8k ----
    #pragma unroll
    for (int idx = tid; idx < K1_MT*K1_KT; idx += K1_THREADS) {
        const int mm = idx >> 3;
        const int kk = idx & 7;
        const int g  = (b*MQ + m0 + mm)*KQ + k0 + kk;
        out[OUT_SDF + g] = sdf_s [kk*K1P + mm];
        out[OUT_SUP + g] = dmin_s[kk*K1P + mm];
        g_occ[g]         = occ_s [kk*K1P + mm];
    }
}

// ============================ K2: intersection (c-split) ==================
// grid: (mtiles=64, chalf=2, b=4) = 512 blocks, 512 threads, single wave.
// Block handles 32 m x 32 c (full k loop). MUFU (EX2) spread over ~2x SMs.
#define K2_MT 32
#define K2_CT 32
#define K2_THREADS 512

// smem floats: occ 64*33=2112 | W 64*32=2048 | int 32*33=1056
#define K2_OFF_OCC 0
#define K2_OFF_W   (64*33)                 // 2112
#define K2_OFF_INT (K2_OFF_W + 64*K2_CT)   // 4160
#define K2_SMEM    (K2_OFF_INT + K2_CT*33) // 5216 floats = 20864 B

__global__ __launch_bounds__(K2_THREADS, 4)
void blend_kernel(const float* __restrict__ Wg,   // (B,K,C)
                  const int*   __restrict__ flag,
                  float* __restrict__ out)
{
    extern __shared__ float sm[];
    float* occ_s = sm + K2_OFF_OCC;   // [k][m], pitch 33
    float* W_s   = sm + K2_OFF_W;     // [k][c_local], pitch 32
    float* int_s = sm + K2_OFF_INT;   // [c_local][m], pitch 33

    const int tid = threadIdx.x;
    const int m0  = blockIdx.x * K2_MT;
    const int c0  = blockIdx.y * K2_CT;
    const int b   = blockIdx.z;

    // occ tile 32m x 64k -> transposed smem
    #pragma unroll
    for (int idx = tid; idx < K2_MT*KQ; idx += K2_THREADS) {
        const int mm = idx >> 6, kk = idx & 63;
        occ_s[kk*33 + mm] = g_occ[(b*MQ + m0 + mm)*KQ + kk];
    }
    // W half: 64k x 32c, coalesced 32-float rows
    #pragma unroll
    for (int idx = tid; idx < KQ*K2_CT; idx += K2_THREADS) {
        const int kk = idx >> 5, cc = idx & 31;
        W_s[kk*K2_CT + cc] = Wg[b*KQ*CQ + kk*CQ + c0 + cc];
    }
    __syncthreads();

    // ---- Phase B: m = tid&31, warp cq handles c_local = cq*2, cq*2+1 ----
    const int training = flag ? *flag : 1;
    const int m_local = tid & 31;
    const int cq      = tid >> 5;      // 0..15, warp-uniform
    const int cl0     = cq * 2;
    if (training) {
        float se0 = 0.f, se1 = 0.f, sp0 = 0.f, sp1 = 0.f;
        #pragma unroll 8
        for (int k = 0; k < KQ; k++) {
            float o   = occ_s[k*33 + m_local];
            float2 wv = *(const float2*)(W_s + k*K2_CT + cl0);  // LDS.64 bcast
            float om = 1.0f - o;
            float t  = 57.707801f * om;                // 40*log2e*(1-o)
            float e0 = ex2f(wv.x * t), p0 = fmaf(-wv.x, om, 1.0f);
            float e1 = ex2f(wv.y * t), p1 = fmaf(-wv.y, om, 1.0f);
            se0 += e0; sp0 = fmaf(e0, p0, sp0);
            se1 += e1; sp1 = fmaf(e1, p1, sp1);
        }
        int_s[(cl0+0)*33 + m_local] = __fdividef(sp0, se0);
        int_s[(cl0+1)*33 + m_local] = __fdividef(sp1, se1);
    } else {
        float mn0 = 3.0e38f, mn1 = 3.0e38f;
        #pragma unroll 8
        for (int k = 0; k < KQ; k++) {
            float o   = occ_s[k*33 + m_local];
            float2 wv = *(const float2*)(W_s + k*K2_CT + cl0);
            float om = 1.0f - o;
            mn0 = fminf(mn0, fmaf(-wv.x, om, 1.0f));
            mn1 = fminf(mn1, fmaf(-wv.y, om, 1.0f));
        }
        int_s[(cl0+0)*33 + m_local] = mn0;
        int_s[(cl0+1)*33 + m_local] = mn1;
    }
    __syncthreads();

    // ---- Flush inter coalesced: 32m x 32c ----
    #pragma unroll
    for (int idx = tid; idx < K2_MT*K2_CT; idx += K2_THREADS) {
        const int mm = idx >> 5, cc = idx & 31;
        out[OUT_INTER + (b*MQ + m0 + mm)*CQ + c0 + cc] = int_s[cc*33 + mm];
    }
}

// ============================ K3: union over c ============================
// grid: 512 blocks x 512 threads; warp per point m. Reads inter from out
// (L2-hot, just written), shuffle-reduces over 64 c. Also resets g_flag.
__global__ __launch_bounds__(512, 4)
void union_kernel(const float* __restrict__ Ug,   // (B,C)
                  const int*   __restrict__ flag,
                  float* __restrict__ out)
{
    const int tid  = threadIdx.x;
    const int wid  = tid >> 5;
    const int lane = tid & 31;

    if (blockIdx.x == 0 && tid < 32) g_flag[tid] = 0;   // reset for next replay

    const int m  = blockIdx.x * 16 + wid;    // 0..8191
    const int b  = m >> 11;
    const float* row = out + OUT_INTER + m * CQ;

    const float u0 = __ldg(Ug + b*CQ + lane);
    const float u1 = __ldg(Ug + b*CQ + lane + 32);
    const float v0 = u0 * row[lane];
    const float v1 = u1 * row[lane + 32];

    float mx = fmaxf(v0, v1);
    #pragma unroll
    for (int off = 16; off > 0; off >>= 1)
        mx = fmaxf(mx, __shfl_xor_sync(0xFFFFFFFF, mx, off));

    const int training = flag ? *flag : 1;
    float e0 = ex2f(57.707801f * (v0 - mx));
    float e1 = ex2f(57.707801f * (v1 - mx));
    float se = e0 + e1;
    float sp = fmaf(e0, v0, e1 * v1);
    #pragma unroll
    for (int off = 16; off > 0; off >>= 1) {
        se += __shfl_xor_sync(0xFFFFFFFF, se, off);
        sp += __shfl_xor_sync(0xFFFFFFFF, sp, off);
    }
    if (lane == 0)
        out[OUT_OCC + m] = training ? __fdividef(sp, se) : mx;
}

extern "C" void kernel_launch(void* const* d_in, const int* in_sizes, int n_in,
                              void* d_out, int out_size) {
    const float* pts  = (const float*)d_in[0];
    const float* prim = (const float*)d_in[1];
    const float* Wg   = (const float*)d_in[2];
    const float* Ug   = (const float*)d_in[3];
    const int*   flag = (n_in >= 5) ? (const int*)d_in[4] : nullptr;
    float* out = (float*)d_out;

    cudaFuncSetAttribute(sdf_kernel,
        cudaFuncAttributeMaxDynamicSharedMemorySize, (int)(K1_SMEM*sizeof(float)));
    cudaFuncSetAttribute(blend_kernel,
        cudaFuncAttributeMaxDynamicSharedMemorySize, (int)(K2_SMEM*sizeof(float)));

    dim3 g1(32, MQ / K1_MT);               // 1024 blocks
    sdf_kernel<<<g1, K1_THREADS, K1_SMEM*sizeof(float)>>>(pts, prim, out);

    dim3 g2(MQ / K2_MT, 2, BQ);            // 64 x 2 x 4 = 512 blocks
    blend_kernel<<<g2, K2_THREADS, K2_SMEM*sizeof(float)>>>(Wg, flag, out);

    union_kernel<<<BQ*MQ/16, 512>>>(Ug, flag, out);   // 512 blocks
}

// round 16
// speedup vs baseline: 1.0656x; 1.0656x over previous
#include <cuda_runtime.h>
#include <math.h>

// Problem constants
#define BQ 4
#define MQ 2048
#define KQ 64
#define CQ 64
#define SRQ 16
#define PPQ 28

// Output layout: occ (B,M) | sdf (B,M,K) | inter (B,M,C) | support (B,M,K)
#define OUT_OCC   0
#define OUT_SDF   (BQ*MQ)
#define OUT_INTER (OUT_SDF + BQ*MQ*KQ)
#define OUT_SUP   (OUT_INTER + BQ*MQ*CQ)

// Inter-kernel / intra-grid scratch (static __device__, allocation-free)
__device__ float  g_occ[BQ*MQ*KQ];          // 2 MB
__device__ float2 g_curve[BQ*KQ*64];        // 128 KB
__device__ float  g_prim[BQ*KQ*8];          // 8 KB
__device__ int    g_flag[32];               // per-(b,ktile8) ready flags

__device__ __forceinline__ float ex2f(float x) {
    float r;
    asm("ex2.approx.ftz.f32 %0, %1;" : "=f"(r) : "f"(x));
    return r;
}

// winding edge, BIT-PARITY form (see R12): crossing needs only signs;
// one LOP3 for (ryb^nyb)&(crb^nyb), one LOP3 XOR-accumulate.
#define EDGE2(rx, ry, parb, nx_, ny_)                                    \
    {                                                                    \
        float cr = fmaf(rx, (ny_), -((ry)*(nx_)));                       \
        parb ^= (__float_as_int(ry) ^ __float_as_int(ny_))               \
              & (__float_as_int(cr) ^ __float_as_int(ny_));              \
        rx = (nx_); ry = (ny_);                                          \
    }

// rotate (x,y) by i*90 degrees (i in 0..3)
__device__ __forceinline__ float2 rot90(int i, float x, float y) {
    switch (i & 3) {
        case 0:  return make_float2( x,  y);
        case 1:  return make_float2(-y,  x);
        case 2:  return make_float2(-x, -y);
        default: return make_float2( y, -x);
    }
}

// theta = 2*pi/16 + atan(tan(2*pi/16)/3) = 0.529902783
#define CT 0.86285621f   // cos(theta)
#define ST 0.50544945f   // sin(theta)

// ============================ K1: SDF =====================================
// grid: (x = b*8+ktile8 = 32, y = mtile = 16) = 512 blocks, 256 threads.
// Block = 8k x 128m; thread = FOUR cells (m, m+32, m+64, m+96) of one k:
// warp k-uniform, ILP4, curve loads amortized 4x, SINGLE WAVE
// (4096 warps over 4736 warp-slots at 4 blocks/SM).
// y==0 blocks are producers: build curve+prim into global, release g_flag[x].
#define K1_MT 128
#define K1_KT 8
#define K1_THREADS 256
#define K1P 129                                  // m-tile pitch

#define K1_OFF_CURVE 0                           // 8*64 float2 = 1024 floats
#define K1_OFF_PRIM  1024                        // 64
#define K1_OFF_SDF   (K1_OFF_PRIM + 64)          // 1088
#define K1_OFF_DMIN  (K1_OFF_SDF + K1_KT*K1P)    // 2120
#define K1_OFF_OCC   (K1_OFF_DMIN + K1_KT*K1P)   // 3152
#define K1_SMEM      (K1_OFF_OCC + K1_KT*K1P)    // 4184 floats = 16736 B

__global__ __launch_bounds__(K1_THREADS, 4)      // 64-reg cap
void sdf_kernel(const float* __restrict__ pts,   // (B,M,3)
                const float* __restrict__ prim,  // (B,28,K)
                float* __restrict__ out)
{
    extern __shared__ float sm[];
    float2* curve  = (float2*)(sm + K1_OFF_CURVE);
    float*  prim_s = sm + K1_OFF_PRIM;
    float*  sdf_s  = sm + K1_OFF_SDF;
    float*  dmin_s = sm + K1_OFF_DMIN;
    float*  occ_s  = sm + K1_OFF_OCC;

    const int tid = threadIdx.x;
    const int bx  = blockIdx.x;            // 0..31 = b*8 + ktile8
    const int b   = bx >> 3;
    const int k0  = (bx & 7) * K1_KT;
    const int m0  = blockIdx.y * K1_MT;

    // ---- Producer blocks (y==0) ----
    if (blockIdx.y == 0) {
        const float* P = prim + b * PPQ * KQ;
        if (tid < K1_KT) {
            const int k = k0 + tid;
            float q0 = P[0*KQ+k], q1 = P[1*KQ+k], q2 = P[2*KQ+k], q3 = P[3*KQ+k];
            float inv = rsqrtf(q0*q0 + q1*q1 + q2*q2 + q3*q3 + 1e-8f);
            float* gp = g_prim + (b*KQ + k)*8;
            gp[0] =  q0*inv;
            gp[1] = -q1*inv;
            gp[2] = -q2*inv;
            gp[3] = -q3*inv;
            gp[4] = P[4*KQ+k];
            gp[5] = P[5*KQ+k];
            gp[6] = P[6*KQ+k];
            gp[7] = fabsf(P[7*KQ+k]);
        }
        #pragma unroll
        for (int half = 0; half < 2; half++) {
            const int p   = tid + half*256;
            const int kli = p >> 6;
            const int k   = k0 + kli;
            const int s   = p & 63;
            const int seg = s >> 4;
            const int j   = s & 15;
            const int sn  = (seg + 1) & 3;
            const float r0 = fabsf(P[(8 + seg*3 + 0)*KQ + k]);
            const float r1 = fabsf(P[(8 + seg*3 + 1)*KQ + k]);
            const float r2 = fabsf(P[(8 + seg*3 + 2)*KQ + k]);
            const float rn = fabsf(P[(8 + sn*3  + 0)*KQ + k]);
            const float w1 = fabsf(P[(20 + seg*2 + 0)*KQ + k]);
            const float w2 = fabsf(P[(20 + seg*2 + 1)*KQ + k]);
            const float2 C0 = rot90(seg,   r0,     0.0f);
            const float2 C1 = rot90(seg,   r1*CT,  r1*ST);
            const float2 C2 = rot90(seg+1, r2*CT, -r2*ST);
            const float2 C3 = rot90(seg+1, rn,     0.0f);
            const float t  = j * (1.0f/SRQ);
            const float u1 = 1.0f - t;
            const float b0 = u1*u1*u1;
            const float b1 = 3.0f*u1*u1*t;
            const float b2 = 3.0f*u1*t*t;
            const float b3 = t*t*t;
            const float wb1 = w1*b1, wb2 = w2*b2;
            const float invd = __fdividef(1.0f, b0 + wb1 + wb2 + b3);
            g_curve[(b*KQ + k)*64 + s] = make_float2(
                (C0.x*b0 + C1.x*wb1 + C2.x*wb2 + C3.x*b3) * invd,
                (C0.y*b0 + C1.y*wb1 + C2.y*wb2 + C3.y*b3) * invd);
        }
        __threadfence();
        __syncthreads();
        if (tid == 0) atomicExch(&g_flag[bx], 1);
    }

    // ---- Acquire + stage curve/prim ----
    if (tid == 0) {
        while (atomicAdd(&g_flag[bx], 0) == 0) { __nanosleep(32); }
    }
    __syncthreads();
    {
        const float4* src = (const float4*)(g_curve + (b*KQ + k0)*64);
        float4* dst = (float4*)curve;
        dst[tid] = __ldcg(src + tid);
    }
    if (tid < K1_KT*8) prim_s[tid] = __ldcg(&g_prim[(b*KQ + k0)*8 + tid]);
    __syncthreads();

    // ---- Phase A: four cells (m, m+32, m+64, m+96) per thread ----
    const int m_local = tid & 31;
    const int kl      = tid >> 5;          // 0..7

    {
        const float* pr = prim_s + kl*8;   // warp-uniform broadcast
        const float qw = pr[0], qx = pr[1], qy = pr[2], qz = pr[3];
        const float tx = pr[4], ty = pr[5], tz = pr[6];
        const float h  = pr[7];

        float plx[4], ply[4], plz[4];
        #pragma unroll
        for (int c = 0; c < 4; c++) {
            const int gm = b*MQ + m0 + m_local + 32*c;
            const float ax = pts[gm*3+0] - tx;
            const float ay = pts[gm*3+1] - ty;
            const float az = pts[gm*3+2] - tz;
            const float t2x = 2.0f*(qy*az - qz*ay);
            const float t2y = 2.0f*(qz*ax - qx*az);
            const float t2z = 2.0f*(qx*ay - qy*ax);
            plx[c] = ax + qw*t2x + (qy*t2z - qz*t2y);
            ply[c] = ay + qw*t2y + (qz*t2x - qx*t2z);
            plz[c] = az + qw*t2z + (qx*t2y - qy*t2x);
        }

        const float4* cvp = (const float4*)(curve + kl*64);
        int   parb[4];
        float rx[4], ry[4], r0x[4], r0y[4], d2a[4], d2b[4];
        float4 f0 = cvp[0];
        #pragma unroll
        for (int c = 0; c < 4; c++) {
            parb[c] = 0;
            r0x[c] = f0.x - plx[c]; r0y[c] = f0.y - ply[c];
            rx[c] = r0x[c]; ry[c] = r0y[c];
            d2a[c] = fmaf(r0x[c], r0x[c], r0y[c]*r0y[c]);
            float bx_ = f0.z - plx[c], by_ = f0.w - ply[c];
            d2b[c] = fmaf(bx_, bx_, by_*by_);
            EDGE2(rx[c], ry[c], parb[c], bx_, by_);
        }
        #pragma unroll 2
        for (int s2 = 1; s2 < 32; s2++) {
            float4 g = cvp[s2];
            #pragma unroll
            for (int c = 0; c < 4; c++) {
                float ax_ = g.x - plx[c], ay_ = g.y - ply[c];
                d2a[c] = fminf(d2a[c], fmaf(ax_, ax_, ay_*ay_));
                EDGE2(rx[c], ry[c], parb[c], ax_, ay_);
                float bx_ = g.z - plx[c], by_ = g.w - ply[c];
                d2b[c] = fminf(d2b[c], fmaf(bx_, bx_, by_*by_));
                EDGE2(rx[c], ry[c], parb[c], bx_, by_);
            }
        }
        #pragma unroll
        for (int c = 0; c < 4; c++) {
            EDGE2(rx[c], ry[c], parb[c], r0x[c], r0y[c]);   // closing edge
            const float d2min = fminf(d2a[c], d2b[c]);
            const float dmin  = sqrtf(d2min + 1e-12f);
            const float sdf2d = __int_as_float(__float_as_int(dmin)
                                               | (parb[c] & 0x80000000));
            const float dz = fabsf(plz[c]) - h;
            const float e1 = fmaxf(sdf2d, 0.0f), e2 = fmaxf(dz, 0.0f);
            const float sdf = fminf(fmaxf(sdf2d, dz), 0.0f)
                            + sqrtf(e1*e1 + e2*e2 + 1e-12f);
            const float ex  = ex2f(fminf(216.404256f * sdf, 126.0f));
            const float occ = __fdividef(1.0f, 1.0f + ex);
            sdf_s [kl*K1P + m_local + 32*c] = sdf;
            dmin_s[kl*K1P + m_local + 32*c] = dmin;
            occ_s [kl*K1P + m_local + 32*c] = occ;
        }
    }
    __syncthreads();

    // ---- Flush coalesced: 128m x 8k (4 iters/thread) ----
    #pragma unroll
    for (int idx = tid; idx < K1_MT*K1_KT; idx += K1_THREADS) {
        const int mm = idx >> 3;           // 0..127
        const int kk = idx & 7;            // 0..7
        const int g  = (b*MQ + m0 + mm)*KQ + k0 + kk;
        out[OUT_SDF + g] = sdf_s [kk*K1P + mm];
        out[OUT_SUP + g] = dmin_s[kk*K1P + mm];
        g_occ[g]         = occ_s [kk*K1P + mm];
    }
}

// ============================ K2: blend (R14 monolithic) ==================
// grid: (mtiles=64, b=4) = 256 blocks, 512 threads
#define K2_MT 32
#define K2_THREADS 512

// smem floats: occ 64*33 | W 64*64 | U 64 | inter 64*33
#define K2_OFF_OCC 0
#define K2_OFF_W   (64*33)                 // 2112
#define K2_OFF_U   (K2_OFF_W + 4096)       // 6208
#define K2_OFF_INT (K2_OFF_U + 64)         // 6272
#define K2_SMEM    (K2_OFF_INT + 64*33)    // 8384 floats = 33536 B

__global__ __launch_bounds__(K2_THREADS, 4)
void blend_kernel(const float* __restrict__ Wg,   // (B,K,C)
                  const float* __restrict__ Ug,   // (B,C)
                  const int*   __restrict__ flag,
                  float* __restrict__ out)
{
    extern __shared__ float sm[];
    float* occ_s = sm + K2_OFF_OCC;   // [k][m], pitch 33
    float* W_s   = sm + K2_OFF_W;     // [k][c]
    float* u_s   = sm + K2_OFF_U;
    float* int_s = sm + K2_OFF_INT;   // [c][m], pitch 33

    const int tid = threadIdx.x;
    const int m0  = blockIdx.x * K2_MT;
    const int b   = blockIdx.y;

    // occ tile 32m x 64k -> transposed smem
    #pragma unroll
    for (int idx = tid; idx < K2_MT*KQ; idx += K2_THREADS) {
        const int mm = idx >> 6, kk = idx & 63;
        occ_s[kk*33 + mm] = g_occ[(b*MQ + m0 + mm)*KQ + kk];
    }
    {   // W coalesced float4
        const float4* src = (const float4*)(Wg + b*KQ*CQ);
        float4* dst = (float4*)W_s;
        dst[tid]       = src[tid];
        dst[tid + 512] = src[tid + 512];
    }
    if (tid < CQ) u_s[tid] = Ug[b*CQ + tid];
    __syncthreads();

    // ---- Phase B: m = tid&31, warp-group cq handles c = cq*4 .. cq*4+3 ----
    const int training = flag ? *flag : 1;
    const int m_local = tid & 31;
    const int cq      = tid >> 5;      // 0..15, warp-uniform
    const float* Wp   = W_s + cq*4;
    if (training) {
        float se0 = 0.f, se1 = 0.f, se2 = 0.f, se3 = 0.f;
        float sp0 = 0.f, sp1 = 0.f, sp2 = 0.f, sp3 = 0.f;
        #pragma unroll 4
        for (int k = 0; k < KQ; k++) {
            float o   = occ_s[k*33 + m_local];
            float4 wv = *(const float4*)(Wp + k*CQ);   // LDS.128 broadcast
            float om = 1.0f - o;
            float t  = 57.707801f * om;                // 40*log2e*(1-o)
            float e0 = ex2f(wv.x * t), p0 = fmaf(-wv.x, om, 1.0f);
            float e1 = ex2f(wv.y * t), p1 = fmaf(-wv.y, om, 1.0f);
            float e2 = ex2f(wv.z * t), p2 = fmaf(-wv.z, om, 1.0f);
            float e3 = ex2f(wv.w * t), p3 = fmaf(-wv.w, om, 1.0f);
            se0 += e0; sp0 = fmaf(e0, p0, sp0);
            se1 += e1; sp1 = fmaf(e1, p1, sp1);
            se2 += e2; sp2 = fmaf(e2, p2, sp2);
            se3 += e3; sp3 = fmaf(e3, p3, sp3);
        }
        int_s[(cq*4+0)*33 + m_local] = __fdividef(sp0, se0);
        int_s[(cq*4+1)*33 + m_local] = __fdividef(sp1, se1);
        int_s[(cq*4+2)*33 + m_local] = __fdividef(sp2, se2);
        int_s[(cq*4+3)*33 + m_local] = __fdividef(sp3, se3);
    } else {
        float mn0 = 3.0e38f, mn1 = 3.0e38f, mn2 = 3.0e38f, mn3 = 3.0e38f;
        #pragma unroll 4
        for (int k = 0; k < KQ; k++) {
            float o   = occ_s[k*33 + m_local];
            float4 wv = *(const float4*)(Wp + k*CQ);
            float om = 1.0f - o;
            mn0 = fminf(mn0, fmaf(-wv.x, om, 1.0f));
            mn1 = fminf(mn1, fmaf(-wv.y, om, 1.0f));
            mn2 = fminf(mn2, fmaf(-wv.z, om, 1.0f));
            mn3 = fminf(mn3, fmaf(-wv.w, om, 1.0f));
        }
        int_s[(cq*4+0)*33 + m_local] = mn0;
        int_s[(cq*4+1)*33 + m_local] = mn1;
        int_s[(cq*4+2)*33 + m_local] = mn2;
        int_s[(cq*4+3)*33 + m_local] = mn3;
    }
    __syncthreads();

    // ---- Flush inter coalesced ----
    const int outbase = (b*MQ + m0) * CQ;
    #pragma unroll
    for (int idx = tid; idx < K2_MT*CQ; idx += K2_THREADS) {
        const int mm = idx >> 6, cc = idx & 63;
        out[OUT_INTER + outbase + idx] = int_s[cc*33 + mm];
    }

    // ---- Phase C: warp w handles m = 2w, 2w+1; lanes reduce over c ----
    const int wid  = tid >> 5;
    const int lane = tid & 31;
    #pragma unroll
    for (int r = 0; r < 2; r++) {
        const int mm = wid*2 + r;
        float v0 = u_s[lane]      * int_s[(lane)   *33 + mm];
        float v1 = u_s[lane + 32] * int_s[(lane+32)*33 + mm];
        float mx = fmaxf(v0, v1);
        #pragma unroll
        for (int off = 16; off > 0; off >>= 1)
            mx = fmaxf(mx, __shfl_xor_sync(0xFFFFFFFF, mx, off));
        float e0 = ex2f(57.707801f * (v0 - mx));
        float e1 = ex2f(57.707801f * (v1 - mx));
        float se = e0 + e1;
        float sp = fmaf(e0, v0, e1 * v1);
        #pragma unroll
        for (int off = 16; off > 0; off >>= 1) {
            se += __shfl_xor_sync(0xFFFFFFFF, se, off);
            sp += __shfl_xor_sync(0xFFFFFFFF, sp, off);
        }
        if (lane == 0)
            out[OUT_OCC + b*MQ + m0 + mm] = training ? __fdividef(sp, se) : mx;
    }
}

// ============================ K3: cleanup =================================
__global__ void cleanup_kernel()
{
    if (threadIdx.x < 32) g_flag[threadIdx.x] = 0;
}

extern "C" void kernel_launch(void* const* d_in, const int* in_sizes, int n_in,
                              void* d_out, int out_size) {
    const float* pts  = (const float*)d_in[0];
    const float* prim = (const float*)d_in[1];
    const float* Wg   = (const float*)d_in[2];
    const float* Ug   = (const float*)d_in[3];
    const int*   flag = (n_in >= 5) ? (const int*)d_in[4] : nullptr;
    float* out = (float*)d_out;

    cudaFuncSetAttribute(sdf_kernel,
        cudaFuncAttributeMaxDynamicSharedMemorySize, (int)(K1_SMEM*sizeof(float)));
    cudaFuncSetAttribute(blend_kernel,
        cudaFuncAttributeMaxDynamicSharedMemorySize, (int)(K2_SMEM*sizeof(float)));

    dim3 g1(32, MQ / K1_MT);               // 32 x 16 = 512 blocks, single wave
    sdf_kernel<<<g1, K1_THREADS, K1_SMEM*sizeof(float)>>>(pts, prim, out);

    dim3 g2(MQ / K2_MT, BQ);               // 64 x 4 = 256 blocks
    blend_kernel<<<g2, K2_THREADS, K2_SMEM*sizeof(float)>>>(Wg, Ug, flag, out);

    cleanup_kernel<<<1, 32>>>();
}